// round 8
// baseline (speedup 1.0000x reference)
#include <cuda_runtime.h>
#include <cstdint>

#define NROWS 8192
#define L2E 1.44269504088896340736f

// ---------------- scratch ----------------
__device__ __align__(16) unsigned g_mask[NROWS * 256];   // 8 MB bitmask
__device__ __align__(16) float g_h[4 * NROWS * 64];      // per-head h = x@Wh
__device__ __align__(16) float g_xcat[NROWS * 256];      // concat LR(head outputs)
__device__ __align__(16) float g_h2[NROWS * 16];         // xcat@Wo
__device__ __align__(16) float g_f1[5 * NROWS];          // f1 * log2e per layer
__device__ __align__(16) float g_f2[5 * NROWS];          // f2 * log2e per layer
__device__ __align__(16) float2 g_b2[5 * NROWS];         // {2^f2, 2^(0.2 f2)}
__device__ __align__(16) float2 g_a[5 * NROWS];          // {2^(f1-m), 2^(0.2 f1 - m)}
__device__ __align__(16) float g_hp[16 * NROWS * 64];    // heads partials
__device__ __align__(16) float g_hpZ[16 * NROWS];
__device__ __align__(16) float g_part[8 * NROWS * 16];   // final-layer partials
__device__ __align__(16) float g_partZ[8 * NROWS];

// ---------------- helpers ----------------
__device__ __forceinline__ float ex2f(float x) {
    float r; asm("ex2.approx.ftz.f32 %0, %1;" : "=f"(r) : "f"(x)); return r;
}
__device__ __forceinline__ unsigned long long pk2(float a, float b) {
    unsigned long long r; asm("mov.b64 %0, {%1, %2};" : "=l"(r) : "f"(a), "f"(b)); return r;
}
__device__ __forceinline__ void up2(unsigned long long v, float& a, float& b) {
    asm("mov.b64 {%0, %1}, %2;" : "=f"(a), "=f"(b) : "l"(v));
}
__device__ __forceinline__ void fma2(unsigned long long& d, unsigned long long a, unsigned long long b) {
    asm("fma.rn.f32x2 %0, %1, %2, %0;" : "+l"(d) : "l"(a), "l"(b));
}
__device__ __forceinline__ void mul2(unsigned long long& d, unsigned long long a, unsigned long long b) {
    asm("mul.rn.f32x2 %0, %1, %2;" : "=l"(d) : "l"(a), "l"(b));
}
__device__ __forceinline__ void lds2u64(const float* p, unsigned long long& a, unsigned long long& b) {
    unsigned sa = (unsigned)__cvta_generic_to_shared(p);
    asm volatile("ld.shared.v2.u64 {%0, %1}, [%2];" : "=l"(a), "=l"(b) : "r"(sa));
}
__device__ __forceinline__ unsigned long long lds1u64(const float* p) {
    unsigned sa = (unsigned)__cvta_generic_to_shared(p);
    unsigned long long r;
    asm volatile("ld.shared.b64 %0, [%1];" : "=l"(r) : "r"(sa));
    return r;
}
__device__ __forceinline__ void sts1u64(float* p, unsigned long long v) {
    unsigned sa = (unsigned)__cvta_generic_to_shared(p);
    asm volatile("st.shared.b64 [%0], %1;" :: "r"(sa), "l"(v));
}

// ---------------- 1) pack adjacency ----------------
__global__ void __launch_bounds__(256) pack_adj_kernel(const int* __restrict__ adj) {
    const int lane = threadIdx.x & 31;
    const int wid = (blockIdx.x * blockDim.x + threadIdx.x) >> 5;
    const int nWarps = (gridDim.x * blockDim.x) >> 5;
    for (int w = wid; w < NROWS * 256; w += nWarps) {
        int v = adj[(size_t)w * 32 + lane];
        unsigned b = __ballot_sync(0xffffffffu, v > 0);
        if (lane == 0) g_mask[w] = b;
    }
}

// ---------------- 2) h = x @ Wh[head] (8192x512x64) ----------------
__global__ void __launch_bounds__(256) gemm64_kernel(const float* __restrict__ X,
                                                     const float* __restrict__ WhAll) {
    const int head = blockIdx.y;
    const float* W = WhAll + head * (512 * 64);
    float* C = g_h + head * (NROWS * 64);
    const int r0 = blockIdx.x * 64;
    const int tid = threadIdx.x;
    __shared__ float4 As4[512];
    __shared__ float4 Bs4[512];
    float* As = (float*)As4;
    const int tr = tid >> 4, tc = tid & 15;
    const int lm = tid & 63, kg = tid >> 6;
    float acc[4][4];
#pragma unroll
    for (int i = 0; i < 4; i++)
#pragma unroll
        for (int j = 0; j < 4; j++) acc[i][j] = 0.f;

    for (int kt = 0; kt < 512; kt += 32) {
        __syncthreads();
        const float* xb = X + (size_t)(r0 + lm) * 512 + kt + kg * 8;
        float4 a0 = ((const float4*)xb)[0];
        float4 a1 = ((const float4*)xb)[1];
        As[(kg * 8 + 0) * 64 + lm] = a0.x; As[(kg * 8 + 1) * 64 + lm] = a0.y;
        As[(kg * 8 + 2) * 64 + lm] = a0.z; As[(kg * 8 + 3) * 64 + lm] = a0.w;
        As[(kg * 8 + 4) * 64 + lm] = a1.x; As[(kg * 8 + 5) * 64 + lm] = a1.y;
        As[(kg * 8 + 6) * 64 + lm] = a1.z; As[(kg * 8 + 7) * 64 + lm] = a1.w;
        const float4* wsrc = (const float4*)(W + kt * 64);
        Bs4[tid] = wsrc[tid];
        Bs4[tid + 256] = wsrc[tid + 256];
        __syncthreads();
#pragma unroll
        for (int kk = 0; kk < 32; kk++) {
            float4 av = As4[kk * 16 + tr];
            float4 bv = Bs4[kk * 16 + tc];
            float aa[4] = {av.x, av.y, av.z, av.w};
            float bb[4] = {bv.x, bv.y, bv.z, bv.w};
#pragma unroll
            for (int i = 0; i < 4; i++)
#pragma unroll
                for (int j = 0; j < 4; j++) acc[i][j] += aa[i] * bb[j];
        }
    }
#pragma unroll
    for (int i = 0; i < 4; i++) {
        float4 o = make_float4(acc[i][0], acc[i][1], acc[i][2], acc[i][3]);
        *(float4*)(C + (size_t)(r0 + tr * 4 + i) * 64 + tc * 4) = o;
    }
}

// ---------------- 3) f1/f2 (log2-scaled) ----------------
__global__ void __launch_bounds__(256) f1f2_heads_kernel(const float* __restrict__ ah) {
    const int head = blockIdx.y;
    const float* H = g_h + head * (NROWS * 64);
    const float* a = ah + head * 128;
    const int lane = threadIdx.x & 31;
    const int row = blockIdx.x * 8 + (threadIdx.x >> 5);
    float h0 = H[row * 64 + lane], h1 = H[row * 64 + 32 + lane];
    float s1 = h0 * a[lane] + h1 * a[32 + lane];
    float s2 = h0 * a[64 + lane] + h1 * a[96 + lane];
#pragma unroll
    for (int off = 16; off; off >>= 1) {
        s1 += __shfl_xor_sync(0xffffffffu, s1, off);
        s2 += __shfl_xor_sync(0xffffffffu, s2, off);
    }
    if (lane == 0) {
        g_f1[head * NROWS + row] = s1 * L2E;
        g_f2[head * NROWS + row] = s2 * L2E;
    }
}

__global__ void __launch_bounds__(256) f1f2_final_kernel(const float* __restrict__ ao) {
    const int lane = threadIdx.x & 31;
    const int row = blockIdx.x * 8 + (threadIdx.x >> 5);
    float s1 = 0.f, s2 = 0.f;
    if (lane < 16) {
        float h = g_h2[row * 16 + lane];
        s1 = h * ao[lane];
        s2 = h * ao[16 + lane];
    }
#pragma unroll
    for (int off = 16; off; off >>= 1) {
        s1 += __shfl_xor_sync(0xffffffffu, s1, off);
        s2 += __shfl_xor_sync(0xffffffffu, s2, off);
    }
    if (lane == 0) {
        g_f1[4 * NROWS + row] = s1 * L2E;
        g_f2[4 * NROWS + row] = s2 * L2E;
    }
}

// ---------------- 3b) B values per column: {2^f2, 2^(0.2 f2)} ----------------
__global__ void __launch_bounds__(256) bvals_kernel(int layer0) {
    const int layer = layer0 + blockIdx.y;
    const int j = blockIdx.x * 256 + threadIdx.x;
    float f2 = g_f2[layer * NROWS + j];
    g_b2[layer * NROWS + j] = make_float2(ex2f(f2), ex2f(0.2f * f2));
}

// ---------------- 4a) masked row max + A values, 4 heads ----------------
__global__ void __launch_bounds__(256) rowmax4_kernel() {
    const int lane = threadIdx.x & 31;
    const int row = blockIdx.x * 8 + (threadIdx.x >> 5);
    const int sh = (lane & 7) * 4;
    float mx0 = -3.0e38f, mx1 = -3.0e38f, mx2 = -3.0e38f, mx3 = -3.0e38f;
    for (int jb = 0; jb < NROWS; jb += 128) {
        uint4 mw = *(const uint4*)&g_mask[row * 256 + (jb >> 5)];
        unsigned word = (lane < 8) ? mw.x : (lane < 16) ? mw.y : (lane < 24) ? mw.z : mw.w;
        const int j = jb + lane * 4;
        float4 v0 = *(const float4*)&g_f2[0 * NROWS + j];
        float4 v1 = *(const float4*)&g_f2[1 * NROWS + j];
        float4 v2 = *(const float4*)&g_f2[2 * NROWS + j];
        float4 v3 = *(const float4*)&g_f2[3 * NROWS + j];
#pragma unroll
        for (int i = 0; i < 4; i++) {
            bool on = (word >> (sh + i)) & 1u;
            mx0 = fmaxf(mx0, on ? ((const float*)&v0)[i] : -3.0e38f);
            mx1 = fmaxf(mx1, on ? ((const float*)&v1)[i] : -3.0e38f);
            mx2 = fmaxf(mx2, on ? ((const float*)&v2)[i] : -3.0e38f);
            mx3 = fmaxf(mx3, on ? ((const float*)&v3)[i] : -3.0e38f);
        }
    }
#pragma unroll
    for (int off = 16; off; off >>= 1) {
        mx0 = fmaxf(mx0, __shfl_xor_sync(0xffffffffu, mx0, off));
        mx1 = fmaxf(mx1, __shfl_xor_sync(0xffffffffu, mx1, off));
        mx2 = fmaxf(mx2, __shfl_xor_sync(0xffffffffu, mx2, off));
        mx3 = fmaxf(mx3, __shfl_xor_sync(0xffffffffu, mx3, off));
    }
    if (lane == 0) {
        float mx[4] = {mx0, mx1, mx2, mx3};
#pragma unroll
        for (int hd = 0; hd < 4; hd++) {
            float f1v = g_f1[hd * NROWS + row];
            float s = f1v + mx[hd];
            float m = fmaxf(s, 0.2f * s);
            g_a[hd * NROWS + row] = make_float2(ex2f(f1v - m), ex2f(0.2f * f1v - m));
        }
    }
}

// ---------------- 4b) masked row max + A values, final layer ----------------
__global__ void __launch_bounds__(256) rowmax1_kernel() {
    const int lane = threadIdx.x & 31;
    const int row = blockIdx.x * 8 + (threadIdx.x >> 5);
    const int sh = (lane & 7) * 4;
    const float* __restrict__ f2 = g_f2 + 4 * NROWS;
    float mx = -3.0e38f;
    for (int jb = 0; jb < NROWS; jb += 128) {
        uint4 mw = *(const uint4*)&g_mask[row * 256 + (jb >> 5)];
        unsigned word = (lane < 8) ? mw.x : (lane < 16) ? mw.y : (lane < 24) ? mw.z : mw.w;
        float4 v = *(const float4*)&f2[jb + lane * 4];
#pragma unroll
        for (int i = 0; i < 4; i++) {
            bool on = (word >> (sh + i)) & 1u;
            mx = fmaxf(mx, on ? ((const float*)&v)[i] : -3.0e38f);
        }
    }
#pragma unroll
    for (int off = 16; off; off >>= 1) mx = fmaxf(mx, __shfl_xor_sync(0xffffffffu, mx, off));
    if (lane == 0) {
        float f1v = g_f1[4 * NROWS + row];
        float s = f1v + mx;
        float m = fmaxf(s, 0.2f * s);
        g_a[4 * NROWS + row] = make_float2(ex2f(f1v - m), ex2f(0.2f * f1v - m));
    }
}

// ---------------- 5) head attention: row-pair packed FFMA2 GEMM ----------------
// block 128 thr: 256 rows x 64 cols, j-range split*2048..+2047, chunks of 32 j.
// thread k-tile: 16 rows (8 row-pairs) x 8 cols; acc packed f32x2 by row-pair.
// Ps layout: [k][rowgroup(16 rows)*20 floats] (padded); Hdup: [k][colgroup*20] (h,h) pairs.
#define PS 320   // floats per k-row of Ps (16 groups x 20)
#define HS 164   // floats per k-row of Hdup (8 groups x 20 + 4 pad)
__global__ void __launch_bounds__(128) attn_heads_gemm2() {
    extern __shared__ float sm[];
    float* Ps = sm;              // 32 * PS
    float* Hd = sm + 32 * PS;    // 32 * HS
    const int head = blockIdx.y;
    const int split = blockIdx.z;
    const int r0 = blockIdx.x * 256;
    const int tid = threadIdx.x;
    const int rg = tid >> 3;     // 0..15 -> rows rg*16..+15
    const int cg = tid & 7;      // cols cg*8..+7
    const int br = r0 + 2 * tid; // build rows br, br+1

    // A values for build rows (two float2 = one float4)
    float4 avv = *(const float4*)&g_a[head * NROWS + 2 * tid + r0];
    const unsigned long long A0 = pk2(avv.x, avv.y);
    const unsigned long long A1 = pk2(avv.z, avv.w);
    float z0 = 0.f, z1 = 0.f;

    unsigned long long acc[8][8];
#pragma unroll
    for (int r = 0; r < 8; r++)
#pragma unroll
        for (int c = 0; c < 8; c++) acc[r][c] = 0ull;

    const int stgk = tid >> 2;          // staging: k row
    const int stgc = (tid & 3) * 16;    // staging: col base
    const float2* bbase = g_b2 + head * NROWS;

    for (int ch = 0; ch < 64; ch++) {
        const int j0 = split * 2048 + ch * 32;
        __syncthreads();
        // stage Hdup
        {
            const float4* hp4 = (const float4*)(g_h + ((size_t)head * NROWS + j0 + stgk) * 64 + stgc);
            float* hdk = Hd + stgk * HS;
#pragma unroll
            for (int q = 0; q < 4; q++) {
                float4 xv = hp4[q];
                int c = stgc + q * 4;
                float* dst = hdk + (c >> 3) * 20 + (c & 7) * 2;
                *(float4*)dst = make_float4(xv.x, xv.x, xv.y, xv.y);
                *(float4*)(dst + 4) = make_float4(xv.z, xv.z, xv.w, xv.w);
            }
        }
        // build P rows br, br+1 (max-form, z folded)
        {
            unsigned w0 = g_mask[(size_t)br * 256 + (j0 >> 5)];
            unsigned w1 = g_mask[(size_t)(br + 1) * 256 + (j0 >> 5)];
            const float2* bp = bbase + j0;
            const int i = 2 * tid;
            float* pdst = Ps + (i >> 4) * 20 + (i & 15);
#pragma unroll 8
            for (int jj = 0; jj < 32; jj++) {
                float2 bv = bp[jj];
                unsigned long long B = pk2(bv.x, bv.y);
                unsigned long long m0, m1;
                mul2(m0, A0, B);
                mul2(m1, A1, B);
                float q0l, q0h, q1l, q1h;
                up2(m0, q0l, q0h);
                up2(m1, q1l, q1h);
                float v0 = fmaxf(q0l, q0h);
                float v1 = fmaxf(q1l, q1h);
                float p0 = ((w0 >> jj) & 1u) ? v0 : 0.f;
                float p1 = ((w1 >> jj) & 1u) ? v1 : 0.f;
                z0 += p0; z1 += p1;
                sts1u64(pdst + jj * PS, pk2(p0, p1));
            }
        }
        __syncthreads();
        // k-loop
        const float* pbase = Ps + rg * 20;
        const float* hbase = Hd + cg * 20;
#pragma unroll 2
        for (int k = 0; k < 32; k++) {
            unsigned long long p[8], h[8];
            lds2u64(pbase + k * PS, p[0], p[1]);
            lds2u64(pbase + k * PS + 4, p[2], p[3]);
            lds2u64(pbase + k * PS + 8, p[4], p[5]);
            lds2u64(pbase + k * PS + 12, p[6], p[7]);
            lds2u64(hbase + k * HS, h[0], h[1]);
            lds2u64(hbase + k * HS + 4, h[2], h[3]);
            lds2u64(hbase + k * HS + 8, h[4], h[5]);
            lds2u64(hbase + k * HS + 12, h[6], h[7]);
#pragma unroll
            for (int r = 0; r < 8; r++)
#pragma unroll
                for (int c = 0; c < 8; c++) fma2(acc[r][c], p[r], h[c]);
        }
    }
    // epilogue
    const int base = (split * 4 + head) * NROWS;
#pragma unroll
    for (int r = 0; r < 8; r++) {
        float lo[8], hi[8];
#pragma unroll
        for (int c = 0; c < 8; c++) up2(acc[r][c], lo[c], hi[c]);
        float* op0 = g_hp + ((size_t)base + r0 + rg * 16 + 2 * r) * 64 + cg * 8;
        float* op1 = op0 + 64;
        *(float4*)op0 = make_float4(lo[0], lo[1], lo[2], lo[3]);
        *(float4*)(op0 + 4) = make_float4(lo[4], lo[5], lo[6], lo[7]);
        *(float4*)op1 = make_float4(hi[0], hi[1], hi[2], hi[3]);
        *(float4*)(op1 + 4) = make_float4(hi[4], hi[5], hi[6], hi[7]);
    }
    g_hpZ[base + br] = z0;
    g_hpZ[base + br + 1] = z1;
}

// ---------------- 5b) reduce head partials -> xcat (LR 0.01) ----------------
__global__ void __launch_bounds__(256) reduce_heads_kernel() {
    const int idx = blockIdx.x * 256 + threadIdx.x;
    const int row = idx >> 8;
    const int cc = idx & 255;
    const int head = cc >> 6;
    const int col = cc & 63;
    float s = 0.f, z = 0.f;
#pragma unroll
    for (int sp = 0; sp < 4; sp++) {
        s += g_hp[((size_t)(sp * 4 + head) * NROWS + row) * 64 + col];
        z += g_hpZ[(sp * 4 + head) * NROWS + row];
    }
    float v = s / z;
    g_xcat[(size_t)row * 256 + cc] = fmaxf(v, 0.01f * v);
}

// ---------------- 6) h2 = xcat @ Wo ----------------
__global__ void __launch_bounds__(128) gemm2_kernel(const float* __restrict__ Wo) {
    __shared__ float Ws[256 * 16];
    const int tid = threadIdx.x;
    for (int i = tid; i < 4096; i += 128) Ws[i] = Wo[i];
    __syncthreads();
    const int row = blockIdx.x * 128 + tid;
    const float* xr = g_xcat + (size_t)row * 256;
    float acc[16];
#pragma unroll
    for (int j = 0; j < 16; j++) acc[j] = 0.f;
    for (int k = 0; k < 256; k += 4) {
        float4 xv = *(const float4*)(xr + k);
#pragma unroll
        for (int j = 0; j < 16; j++) {
            acc[j] += xv.x * Ws[(k + 0) * 16 + j];
            acc[j] += xv.y * Ws[(k + 1) * 16 + j];
            acc[j] += xv.z * Ws[(k + 2) * 16 + j];
            acc[j] += xv.w * Ws[(k + 3) * 16 + j];
        }
    }
#pragma unroll
    for (int j = 0; j < 16; j++) g_h2[row * 16 + j] = acc[j];
}

// ---------------- 7) final attention (FFMA2 tiled GEMM, max-form) ----------------
#define PSTRIDE 132
__global__ void __launch_bounds__(128) attn_final_gemm() {
    const int split = blockIdx.y;
    const int r0 = blockIdx.x * 128;
    const int tid = threadIdx.x;
    const int tr = tid >> 3;
    const int tc = tid & 7;
    const int jj = tid & 31;
    const int quarter = tid >> 5;

    __shared__ float Ps[32 * PSTRIDE];
    __shared__ float Hs[32 * 16];
    __shared__ float Aps[128], Ams[128];
    __shared__ unsigned mws[128];

    if (tid < 128) {
        float2 av = g_a[4 * NROWS + r0 + tid];
        Aps[tid] = av.x; Ams[tid] = av.y;
    }
    unsigned long long acc[8];
#pragma unroll
    for (int r = 0; r < 8; r++) acc[r] = 0ull;
    float zrow = 0.f;

    const int jbase = split * 1024;
    for (int ch = 0; ch < 32; ch++) {
        const int j0 = jbase + ch * 32;
        __syncthreads();
        {
            const float4* src = (const float4*)(g_h2 + (size_t)j0 * 16);
            if (tid < 128) ((float4*)Hs)[tid] = src[tid];
        }
        mws[tid] = g_mask[(size_t)(r0 + tid) * 256 + (j0 >> 5)];
        float2 bv = g_b2[4 * NROWS + j0 + jj];
        const float Bpr = bv.x, Bmr = bv.y;
        __syncthreads();
        {
            const int i0 = quarter * 32;
            float* prow = Ps + jj * PSTRIDE;
#pragma unroll
            for (int ib = 0; ib < 32; ib += 4) {
                float pv[4];
#pragma unroll
                for (int ii = 0; ii < 4; ii++) {
                    const int i = i0 + ib + ii;
                    float v = fmaxf(Aps[i] * Bpr, Ams[i] * Bmr);
                    pv[ii] = ((mws[i] >> jj) & 1u) ? v : 0.f;
                }
                *(float4*)(prow + i0 + ib) = make_float4(pv[0], pv[1], pv[2], pv[3]);
            }
        }
        __syncthreads();
#pragma unroll 2
        for (int k = 0; k < 32; k++) {
            float4 pa = *(const float4*)(Ps + k * PSTRIDE + tr * 8);
            float4 pb = *(const float4*)(Ps + k * PSTRIDE + tr * 8 + 4);
            unsigned long long h0 = lds1u64(Hs + k * 16 + tc * 2);
            unsigned long long p2[8];
            p2[0] = pk2(pa.x, pa.x); p2[1] = pk2(pa.y, pa.y);
            p2[2] = pk2(pa.z, pa.z); p2[3] = pk2(pa.w, pa.w);
            p2[4] = pk2(pb.x, pb.x); p2[5] = pk2(pb.y, pb.y);
            p2[6] = pk2(pb.z, pb.z); p2[7] = pk2(pb.w, pb.w);
#pragma unroll
            for (int r = 0; r < 8; r++) fma2(acc[r], p2[r], h0);
        }
        {
            float zs = 0.f;
#pragma unroll 8
            for (int k = 0; k < 32; k++) zs += Ps[k * PSTRIDE + tid];
            zrow += zs;
        }
    }
#pragma unroll
    for (int r = 0; r < 8; r++) {
        const int row = r0 + tr * 8 + r;
        *(unsigned long long*)&g_part[((size_t)split * NROWS + row) * 16 + tc * 2] = acc[r];
    }
    g_partZ[split * NROWS + r0 + tid] = zrow;
}

// ---------------- 8) reduce partials -> output ----------------
__global__ void __launch_bounds__(256) reduce_kernel(float* __restrict__ out) {
    const int idx = blockIdx.x * 256 + threadIdx.x;
    const int row = idx >> 4;
    float s = 0.f, z = 0.f;
#pragma unroll
    for (int c = 0; c < 8; c++) {
        s += g_part[((size_t)c * NROWS + row) * 16 + (idx & 15)];
        z += g_partZ[c * NROWS + row];
    }
    out[idx] = s / z;
}

extern "C" void kernel_launch(void* const* d_in, const int* in_sizes, int n_in,
                              void* d_out, int out_size) {
    const float* x   = (const float*)d_in[0];
    const int*   adj = (const int*)d_in[1];
    const float* Wh  = (const float*)d_in[2];
    const float* ah  = (const float*)d_in[3];
    const float* Wo  = (const float*)d_in[4];
    const float* ao  = (const float*)d_in[5];
    float* out = (float*)d_out;

    const int smemBytes = (32 * PS + 32 * HS) * 4;  // 61952
    cudaFuncSetAttribute(attn_heads_gemm2, cudaFuncAttributeMaxDynamicSharedMemorySize, smemBytes);

    pack_adj_kernel<<<2048, 256>>>(adj);
    gemm64_kernel<<<dim3(128, 4), 256>>>(x, Wh);
    f1f2_heads_kernel<<<dim3(1024, 4), 256>>>(ah);
    bvals_kernel<<<dim3(32, 4), 256>>>(0);
    rowmax4_kernel<<<1024, 256>>>();
    attn_heads_gemm2<<<dim3(32, 4, 4), 128, smemBytes>>>();
    reduce_heads_kernel<<<8192, 256>>>();
    gemm2_kernel<<<64, 128>>>(Wo);
    f1f2_final_kernel<<<1024, 256>>>(ao);
    bvals_kernel<<<dim3(32, 1), 256>>>(4);
    rowmax1_kernel<<<1024, 256>>>();
    attn_final_gemm<<<dim3(64, 8), 128>>>();
    reduce_kernel<<<512, 256>>>(out);
}

// round 9
// speedup vs baseline: 1.0389x; 1.0389x over previous
#include <cuda_runtime.h>
#include <cstdint>

#define NROWS 8192
#define L2E 1.44269504088896340736f

// ---------------- scratch ----------------
__device__ __align__(16) unsigned g_mask[NROWS * 256];   // 8 MB bitmask
__device__ __align__(16) float g_h[4 * NROWS * 64];      // per-head h = x@Wh
__device__ __align__(16) float g_xcat[NROWS * 256];      // concat LR(head outputs)
__device__ __align__(16) float g_h2[NROWS * 16];         // xcat@Wo
__device__ __align__(16) float g_f1[5 * NROWS];          // f1 * log2e per layer
__device__ __align__(16) float g_f2[5 * NROWS];          // f2 * log2e per layer
__device__ __align__(16) float2 g_b2[5 * NROWS];         // {2^f2, 2^(0.2 f2)}
__device__ __align__(16) float2 g_a[5 * NROWS];          // {2^(f1-m), 2^(0.2 f1 - m)}
__device__ __align__(16) float g_hp[16 * NROWS * 64];    // heads partials
__device__ __align__(16) float g_hpZ[16 * NROWS];
__device__ __align__(16) float g_part[8 * NROWS * 16];   // final-layer partials
__device__ __align__(16) float g_partZ[8 * NROWS];

// ---------------- helpers ----------------
__device__ __forceinline__ float ex2f(float x) {
    float r; asm("ex2.approx.ftz.f32 %0, %1;" : "=f"(r) : "f"(x)); return r;
}
__device__ __forceinline__ unsigned long long pk2(float a, float b) {
    unsigned long long r; asm("mov.b64 %0, {%1, %2};" : "=l"(r) : "f"(a), "f"(b)); return r;
}
__device__ __forceinline__ void up2(unsigned long long v, float& a, float& b) {
    asm("mov.b64 {%0, %1}, %2;" : "=f"(a), "=f"(b) : "l"(v));
}
__device__ __forceinline__ void fma2(unsigned long long& d, unsigned long long a, unsigned long long b) {
    asm("fma.rn.f32x2 %0, %1, %2, %0;" : "+l"(d) : "l"(a), "l"(b));
}
__device__ __forceinline__ void mul2(unsigned long long& d, unsigned long long a, unsigned long long b) {
    asm("mul.rn.f32x2 %0, %1, %2;" : "=l"(d) : "l"(a), "l"(b));
}
__device__ __forceinline__ void lds2u64(const float* p, unsigned long long& a, unsigned long long& b) {
    unsigned sa = (unsigned)__cvta_generic_to_shared(p);
    asm volatile("ld.shared.v2.u64 {%0, %1}, [%2];" : "=l"(a), "=l"(b) : "r"(sa));
}
__device__ __forceinline__ unsigned long long lds1u64(const float* p) {
    unsigned sa = (unsigned)__cvta_generic_to_shared(p);
    unsigned long long r;
    asm volatile("ld.shared.b64 %0, [%1];" : "=l"(r) : "r"(sa));
    return r;
}

// ---------------- 1) pack adjacency ----------------
__global__ void __launch_bounds__(256) pack_adj_kernel(const int* __restrict__ adj) {
    const int lane = threadIdx.x & 31;
    const int wid = (blockIdx.x * blockDim.x + threadIdx.x) >> 5;
    const int nWarps = (gridDim.x * blockDim.x) >> 5;
    for (int w = wid; w < NROWS * 256; w += nWarps) {
        int v = adj[(size_t)w * 32 + lane];
        unsigned b = __ballot_sync(0xffffffffu, v > 0);
        if (lane == 0) g_mask[w] = b;
    }
}

// ---------------- 2) h = x @ Wh[head] (8192x512x64) ----------------
__global__ void __launch_bounds__(256) gemm64_kernel(const float* __restrict__ X,
                                                     const float* __restrict__ WhAll) {
    const int head = blockIdx.y;
    const float* W = WhAll + head * (512 * 64);
    float* C = g_h + head * (NROWS * 64);
    const int r0 = blockIdx.x * 64;
    const int tid = threadIdx.x;
    __shared__ float4 As4[512];
    __shared__ float4 Bs4[512];
    float* As = (float*)As4;
    const int tr = tid >> 4, tc = tid & 15;
    const int lm = tid & 63, kg = tid >> 6;
    float acc[4][4];
#pragma unroll
    for (int i = 0; i < 4; i++)
#pragma unroll
        for (int j = 0; j < 4; j++) acc[i][j] = 0.f;

    for (int kt = 0; kt < 512; kt += 32) {
        __syncthreads();
        const float* xb = X + (size_t)(r0 + lm) * 512 + kt + kg * 8;
        float4 a0 = ((const float4*)xb)[0];
        float4 a1 = ((const float4*)xb)[1];
        As[(kg * 8 + 0) * 64 + lm] = a0.x; As[(kg * 8 + 1) * 64 + lm] = a0.y;
        As[(kg * 8 + 2) * 64 + lm] = a0.z; As[(kg * 8 + 3) * 64 + lm] = a0.w;
        As[(kg * 8 + 4) * 64 + lm] = a1.x; As[(kg * 8 + 5) * 64 + lm] = a1.y;
        As[(kg * 8 + 6) * 64 + lm] = a1.z; As[(kg * 8 + 7) * 64 + lm] = a1.w;
        const float4* wsrc = (const float4*)(W + kt * 64);
        Bs4[tid] = wsrc[tid];
        Bs4[tid + 256] = wsrc[tid + 256];
        __syncthreads();
#pragma unroll
        for (int kk = 0; kk < 32; kk++) {
            float4 av = As4[kk * 16 + tr];
            float4 bv = Bs4[kk * 16 + tc];
            float aa[4] = {av.x, av.y, av.z, av.w};
            float bb[4] = {bv.x, bv.y, bv.z, bv.w};
#pragma unroll
            for (int i = 0; i < 4; i++)
#pragma unroll
                for (int j = 0; j < 4; j++) acc[i][j] += aa[i] * bb[j];
        }
    }
#pragma unroll
    for (int i = 0; i < 4; i++) {
        float4 o = make_float4(acc[i][0], acc[i][1], acc[i][2], acc[i][3]);
        *(float4*)(C + (size_t)(r0 + tr * 4 + i) * 64 + tc * 4) = o;
    }
}

// ---------------- 3) f1/f2 + B values (log2-scaled) ----------------
__global__ void __launch_bounds__(256) f1f2_heads_kernel(const float* __restrict__ ah) {
    const int head = blockIdx.y;
    const float* H = g_h + head * (NROWS * 64);
    const float* a = ah + head * 128;
    const int lane = threadIdx.x & 31;
    const int row = blockIdx.x * 8 + (threadIdx.x >> 5);
    float h0 = H[row * 64 + lane], h1 = H[row * 64 + 32 + lane];
    float s1 = h0 * a[lane] + h1 * a[32 + lane];
    float s2 = h0 * a[64 + lane] + h1 * a[96 + lane];
#pragma unroll
    for (int off = 16; off; off >>= 1) {
        s1 += __shfl_xor_sync(0xffffffffu, s1, off);
        s2 += __shfl_xor_sync(0xffffffffu, s2, off);
    }
    if (lane == 0) {
        float f2v = s2 * L2E;
        g_f1[head * NROWS + row] = s1 * L2E;
        g_f2[head * NROWS + row] = f2v;
        g_b2[head * NROWS + row] = make_float2(ex2f(f2v), ex2f(0.2f * f2v));
    }
}

__global__ void __launch_bounds__(256) f1f2_final_kernel(const float* __restrict__ ao) {
    const int lane = threadIdx.x & 31;
    const int row = blockIdx.x * 8 + (threadIdx.x >> 5);
    float s1 = 0.f, s2 = 0.f;
    if (lane < 16) {
        float h = g_h2[row * 16 + lane];
        s1 = h * ao[lane];
        s2 = h * ao[16 + lane];
    }
#pragma unroll
    for (int off = 16; off; off >>= 1) {
        s1 += __shfl_xor_sync(0xffffffffu, s1, off);
        s2 += __shfl_xor_sync(0xffffffffu, s2, off);
    }
    if (lane == 0) {
        float f2v = s2 * L2E;
        g_f1[4 * NROWS + row] = s1 * L2E;
        g_f2[4 * NROWS + row] = f2v;
        g_b2[4 * NROWS + row] = make_float2(ex2f(f2v), ex2f(0.2f * f2v));
    }
}

// ---------------- 4a) masked row max + A values, 4 heads ----------------
__global__ void __launch_bounds__(256) rowmax4_kernel() {
    const int lane = threadIdx.x & 31;
    const int row = blockIdx.x * 8 + (threadIdx.x >> 5);
    const int sh = (lane & 7) * 4;
    float mx0 = -3.0e38f, mx1 = -3.0e38f, mx2 = -3.0e38f, mx3 = -3.0e38f;
    for (int jb = 0; jb < NROWS; jb += 128) {
        uint4 mw = *(const uint4*)&g_mask[row * 256 + (jb >> 5)];
        unsigned word = (lane < 8) ? mw.x : (lane < 16) ? mw.y : (lane < 24) ? mw.z : mw.w;
        const int j = jb + lane * 4;
        float4 v0 = *(const float4*)&g_f2[0 * NROWS + j];
        float4 v1 = *(const float4*)&g_f2[1 * NROWS + j];
        float4 v2 = *(const float4*)&g_f2[2 * NROWS + j];
        float4 v3 = *(const float4*)&g_f2[3 * NROWS + j];
#pragma unroll
        for (int i = 0; i < 4; i++) {
            bool on = (word >> (sh + i)) & 1u;
            mx0 = fmaxf(mx0, on ? ((const float*)&v0)[i] : -3.0e38f);
            mx1 = fmaxf(mx1, on ? ((const float*)&v1)[i] : -3.0e38f);
            mx2 = fmaxf(mx2, on ? ((const float*)&v2)[i] : -3.0e38f);
            mx3 = fmaxf(mx3, on ? ((const float*)&v3)[i] : -3.0e38f);
        }
    }
#pragma unroll
    for (int off = 16; off; off >>= 1) {
        mx0 = fmaxf(mx0, __shfl_xor_sync(0xffffffffu, mx0, off));
        mx1 = fmaxf(mx1, __shfl_xor_sync(0xffffffffu, mx1, off));
        mx2 = fmaxf(mx2, __shfl_xor_sync(0xffffffffu, mx2, off));
        mx3 = fmaxf(mx3, __shfl_xor_sync(0xffffffffu, mx3, off));
    }
    if (lane == 0) {
        float mx[4] = {mx0, mx1, mx2, mx3};
#pragma unroll
        for (int hd = 0; hd < 4; hd++) {
            float f1v = g_f1[hd * NROWS + row];
            float s = f1v + mx[hd];
            float m = fmaxf(s, 0.2f * s);
            g_a[hd * NROWS + row] = make_float2(ex2f(f1v - m), ex2f(0.2f * f1v - m));
        }
    }
}

// ---------------- 4b) masked row max + A values, final layer ----------------
__global__ void __launch_bounds__(256) rowmax1_kernel() {
    const int lane = threadIdx.x & 31;
    const int row = blockIdx.x * 8 + (threadIdx.x >> 5);
    const int sh = (lane & 7) * 4;
    const float* __restrict__ f2 = g_f2 + 4 * NROWS;
    float mx = -3.0e38f;
    for (int jb = 0; jb < NROWS; jb += 128) {
        uint4 mw = *(const uint4*)&g_mask[row * 256 + (jb >> 5)];
        unsigned word = (lane < 8) ? mw.x : (lane < 16) ? mw.y : (lane < 24) ? mw.z : mw.w;
        float4 v = *(const float4*)&f2[jb + lane * 4];
#pragma unroll
        for (int i = 0; i < 4; i++) {
            bool on = (word >> (sh + i)) & 1u;
            mx = fmaxf(mx, on ? ((const float*)&v)[i] : -3.0e38f);
        }
    }
#pragma unroll
    for (int off = 16; off; off >>= 1) mx = fmaxf(mx, __shfl_xor_sync(0xffffffffu, mx, off));
    if (lane == 0) {
        float f1v = g_f1[4 * NROWS + row];
        float s = f1v + mx;
        float m = fmaxf(s, 0.2f * s);
        g_a[4 * NROWS + row] = make_float2(ex2f(f1v - m), ex2f(0.2f * f1v - m));
    }
}

// ---------------- 5) head attention: dup-P FFMA2 GEMM ----------------
// block 128 thr: 128 rows x 64 cols, j-range split*2048..+2047, chunks of 32 j.
// Pd layout: [k][row] duplicated (p,p) u64, stride PDS=260 floats (4-phase stores).
// thread tile: rows tr*8..+7 (tr=tid>>3), cols tc*8..+7 (tc=tid&7).
#define PDS 260
__global__ void __launch_bounds__(128) attn_heads_gemm3() {
    __shared__ float Pd[32 * PDS];   // 33280 B
    __shared__ float Hs[32 * 64];    // 8192 B
    __shared__ float As2[256];       // 128 x float2
    __shared__ unsigned mws[128];
    const int head = blockIdx.y;
    const int split = blockIdx.z;
    const int r0 = blockIdx.x * 128;
    const int tid = threadIdx.x;
    const int tr = tid >> 3;         // 0..15
    const int tc = tid & 7;          // 0..7
    const int jj = tid & 31;         // build column (k index)
    const int i0 = (tid >> 5) * 32;  // build row quarter

    {
        float2 av = g_a[head * NROWS + r0 + tid];
        As2[2 * tid] = av.x;
        As2[2 * tid + 1] = av.y;
    }

    unsigned long long acc[8][4];
#pragma unroll
    for (int r = 0; r < 8; r++)
#pragma unroll
        for (int c = 0; c < 4; c++) acc[r][c] = 0ull;
    float zrow = 0.f;

    for (int ch = 0; ch < 64; ch++) {
        const int j0 = split * 2048 + ch * 32;
        __syncthreads();
        // stage H chunk 32x64
        {
            const float4* src = (const float4*)(g_h + ((size_t)head * NROWS + j0) * 64);
            float4* dst = (float4*)Hs;
#pragma unroll
            for (int v = 0; v < 4; v++) dst[tid + 128 * v] = src[tid + 128 * v];
        }
        mws[tid] = g_mask[(size_t)(r0 + tid) * 256 + (j0 >> 5)];
        float2 bv = g_b2[head * NROWS + j0 + jj];
        const unsigned long long B2 = pk2(bv.x, bv.y);
        __syncthreads();
        // build dup-P column jj for rows i0..i0+31
        {
            float* pcol = Pd + jj * PDS;
#pragma unroll
            for (int i2 = 0; i2 < 32; i2 += 2) {
                const int i = i0 + i2;
                unsigned long long a0 = lds1u64(As2 + 2 * i);
                unsigned long long a1 = lds1u64(As2 + 2 * i + 2);
                unsigned long long m0, m1;
                mul2(m0, a0, B2);
                mul2(m1, a1, B2);
                float x0, y0, x1, y1;
                up2(m0, x0, y0);
                up2(m1, x1, y1);
                float v0 = fmaxf(x0, y0);
                float v1 = fmaxf(x1, y1);
                float p0 = ((mws[i] >> jj) & 1u) ? v0 : 0.f;
                float p1 = ((mws[i + 1] >> jj) & 1u) ? v1 : 0.f;
                *(float4*)(pcol + 2 * i) = make_float4(p0, p0, p1, p1);
            }
        }
        __syncthreads();
        // k-loop: no pk2, P already duplicated
        const float* pbase = Pd + tr * 16;
        const float* hbase = Hs + tc * 8;
#pragma unroll 2
        for (int k = 0; k < 32; k++) {
            unsigned long long p[8], h[4];
            lds2u64(pbase + k * PDS, p[0], p[1]);
            lds2u64(pbase + k * PDS + 4, p[2], p[3]);
            lds2u64(pbase + k * PDS + 8, p[4], p[5]);
            lds2u64(pbase + k * PDS + 12, p[6], p[7]);
            lds2u64(hbase + k * 64, h[0], h[1]);
            lds2u64(hbase + k * 64 + 4, h[2], h[3]);
#pragma unroll
            for (int r = 0; r < 8; r++) {
                fma2(acc[r][0], p[r], h[0]);
                fma2(acc[r][1], p[r], h[1]);
                fma2(acc[r][2], p[r], h[2]);
                fma2(acc[r][3], p[r], h[3]);
            }
        }
        // z pass: row tid
        {
            float zs = 0.f;
#pragma unroll 8
            for (int k = 0; k < 32; k++) zs += Pd[k * PDS + 2 * tid];
            zrow += zs;
        }
    }
    // epilogue
    const int base = (split * 4 + head) * NROWS;
#pragma unroll
    for (int r = 0; r < 8; r++) {
        const int row = r0 + tr * 8 + r;
        float lo0, hi0, lo1, hi1, lo2, hi2, lo3, hi3;
        up2(acc[r][0], lo0, hi0);
        up2(acc[r][1], lo1, hi1);
        up2(acc[r][2], lo2, hi2);
        up2(acc[r][3], lo3, hi3);
        float* op = g_hp + ((size_t)base + row) * 64 + tc * 8;
        *(float4*)op = make_float4(lo0, hi0, lo1, hi1);
        *(float4*)(op + 4) = make_float4(lo2, hi2, lo3, hi3);
    }
    g_hpZ[base + r0 + tid] = zrow;
}

// ---------------- 5b) reduce head partials -> xcat (LR 0.01) ----------------
__global__ void __launch_bounds__(256) reduce_heads_kernel() {
    const int idx = blockIdx.x * 256 + threadIdx.x;
    const int row = idx >> 8;
    const int cc = idx & 255;
    const int head = cc >> 6;
    const int col = cc & 63;
    float s = 0.f, z = 0.f;
#pragma unroll
    for (int sp = 0; sp < 4; sp++) {
        s += g_hp[((size_t)(sp * 4 + head) * NROWS + row) * 64 + col];
        z += g_hpZ[(sp * 4 + head) * NROWS + row];
    }
    float v = s / z;
    g_xcat[(size_t)row * 256 + cc] = fmaxf(v, 0.01f * v);
}

// ---------------- 6) h2 = xcat @ Wo ----------------
__global__ void __launch_bounds__(128) gemm2_kernel(const float* __restrict__ Wo) {
    __shared__ float Ws[256 * 16];
    const int tid = threadIdx.x;
    for (int i = tid; i < 4096; i += 128) Ws[i] = Wo[i];
    __syncthreads();
    const int row = blockIdx.x * 128 + tid;
    const float* xr = g_xcat + (size_t)row * 256;
    float acc[16];
#pragma unroll
    for (int j = 0; j < 16; j++) acc[j] = 0.f;
    for (int k = 0; k < 256; k += 4) {
        float4 xv = *(const float4*)(xr + k);
#pragma unroll
        for (int j = 0; j < 16; j++) {
            acc[j] += xv.x * Ws[(k + 0) * 16 + j];
            acc[j] += xv.y * Ws[(k + 1) * 16 + j];
            acc[j] += xv.z * Ws[(k + 2) * 16 + j];
            acc[j] += xv.w * Ws[(k + 3) * 16 + j];
        }
    }
#pragma unroll
    for (int j = 0; j < 16; j++) g_h2[row * 16 + j] = acc[j];
}

// ---------------- 7) final attention (FFMA2 tiled GEMM, max-form) ----------------
#define PSTRIDE 132
__global__ void __launch_bounds__(128) attn_final_gemm() {
    const int split = blockIdx.y;
    const int r0 = blockIdx.x * 128;
    const int tid = threadIdx.x;
    const int tr = tid >> 3;
    const int tc = tid & 7;
    const int jj = tid & 31;
    const int quarter = tid >> 5;

    __shared__ float Ps[32 * PSTRIDE];
    __shared__ float Hs[32 * 16];
    __shared__ float Aps[128], Ams[128];
    __shared__ unsigned mws[128];

    if (tid < 128) {
        float2 av = g_a[4 * NROWS + r0 + tid];
        Aps[tid] = av.x; Ams[tid] = av.y;
    }
    unsigned long long acc[8];
#pragma unroll
    for (int r = 0; r < 8; r++) acc[r] = 0ull;
    float zrow = 0.f;

    const int jbase = split * 1024;
    for (int ch = 0; ch < 32; ch++) {
        const int j0 = jbase + ch * 32;
        __syncthreads();
        {
            const float4* src = (const float4*)(g_h2 + (size_t)j0 * 16);
            if (tid < 128) ((float4*)Hs)[tid] = src[tid];
        }
        mws[tid] = g_mask[(size_t)(r0 + tid) * 256 + (j0 >> 5)];
        float2 bv = g_b2[4 * NROWS + j0 + jj];
        const float Bpr = bv.x, Bmr = bv.y;
        __syncthreads();
        {
            const int i0 = quarter * 32;
            float* prow = Ps + jj * PSTRIDE;
#pragma unroll
            for (int ib = 0; ib < 32; ib += 4) {
                float pv[4];
#pragma unroll
                for (int ii = 0; ii < 4; ii++) {
                    const int i = i0 + ib + ii;
                    float v = fmaxf(Aps[i] * Bpr, Ams[i] * Bmr);
                    pv[ii] = ((mws[i] >> jj) & 1u) ? v : 0.f;
                }
                *(float4*)(prow + i0 + ib) = make_float4(pv[0], pv[1], pv[2], pv[3]);
            }
        }
        __syncthreads();
#pragma unroll 2
        for (int k = 0; k < 32; k++) {
            float4 pa = *(const float4*)(Ps + k * PSTRIDE + tr * 8);
            float4 pb = *(const float4*)(Ps + k * PSTRIDE + tr * 8 + 4);
            unsigned long long h0 = lds1u64(Hs + k * 16 + tc * 2);
            unsigned long long p2[8];
            p2[0] = pk2(pa.x, pa.x); p2[1] = pk2(pa.y, pa.y);
            p2[2] = pk2(pa.z, pa.z); p2[3] = pk2(pa.w, pa.w);
            p2[4] = pk2(pb.x, pb.x); p2[5] = pk2(pb.y, pb.y);
            p2[6] = pk2(pb.z, pb.z); p2[7] = pk2(pb.w, pb.w);
#pragma unroll
            for (int r = 0; r < 8; r++) fma2(acc[r], p2[r], h0);
        }
        {
            float zs = 0.f;
#pragma unroll 8
            for (int k = 0; k < 32; k++) zs += Ps[k * PSTRIDE + tid];
            zrow += zs;
        }
    }
#pragma unroll
    for (int r = 0; r < 8; r++) {
        const int row = r0 + tr * 8 + r;
        *(unsigned long long*)&g_part[((size_t)split * NROWS + row) * 16 + tc * 2] = acc[r];
    }
    g_partZ[split * NROWS + r0 + tid] = zrow;
}

// ---------------- 8) reduce partials -> output ----------------
__global__ void __launch_bounds__(256) reduce_kernel(float* __restrict__ out) {
    const int idx = blockIdx.x * 256 + threadIdx.x;
    const int row = idx >> 4;
    float s = 0.f, z = 0.f;
#pragma unroll
    for (int c = 0; c < 8; c++) {
        s += g_part[((size_t)c * NROWS + row) * 16 + (idx & 15)];
        z += g_partZ[c * NROWS + row];
    }
    out[idx] = s / z;
}

extern "C" void kernel_launch(void* const* d_in, const int* in_sizes, int n_in,
                              void* d_out, int out_size) {
    const float* x   = (const float*)d_in[0];
    const int*   adj = (const int*)d_in[1];
    const float* Wh  = (const float*)d_in[2];
    const float* ah  = (const float*)d_in[3];
    const float* Wo  = (const float*)d_in[4];
    const float* ao  = (const float*)d_in[5];
    float* out = (float*)d_out;

    pack_adj_kernel<<<2048, 256>>>(adj);
    gemm64_kernel<<<dim3(128, 4), 256>>>(x, Wh);
    f1f2_heads_kernel<<<dim3(1024, 4), 256>>>(ah);
    rowmax4_kernel<<<1024, 256>>>();
    attn_heads_gemm3<<<dim3(64, 4, 4), 128>>>();
    reduce_heads_kernel<<<8192, 256>>>();
    gemm2_kernel<<<64, 128>>>(Wo);
    f1f2_final_kernel<<<1024, 256>>>(ao);
    rowmax1_kernel<<<1024, 256>>>();
    attn_final_gemm<<<dim3(64, 8), 128>>>();
    reduce_kernel<<<512, 256>>>(out);
}

// round 11
// speedup vs baseline: 1.1940x; 1.1492x over previous
#include <cuda_runtime.h>
#include <cstdint>

#define NROWS 8192
#define L2E 1.44269504088896340736f

// ---------------- scratch ----------------
__device__ __align__(16) unsigned g_mask[NROWS * 256];   // 8 MB bitmask
__device__ __align__(16) float g_h[4 * NROWS * 64];      // per-head h = x@Wh
__device__ __align__(16) float g_xcat[NROWS * 256];      // concat LR(head outputs)
__device__ __align__(16) float g_h2[NROWS * 16];         // xcat@Wo
__device__ __align__(16) float g_f1[5 * NROWS];          // f1 * log2e per layer
__device__ __align__(16) float g_f2[5 * NROWS];          // f2 * log2e per layer
__device__ __align__(16) float4 g_fb4[5 * NROWS];        // {f2, 2^f2, 2^(0.2 f2), 0}
__device__ __align__(16) float2 g_a[5 * NROWS];          // {2^(f1-m), 2^(0.2 f1 - m)}
__device__ float g_gmax[5];                              // global max of f2 per layer
__device__ __align__(16) float g_hp[16 * NROWS * 64];    // heads partials
__device__ __align__(16) float g_hpZ[16 * NROWS];
__device__ __align__(16) float g_part[8 * NROWS * 16];   // final-layer partials
__device__ __align__(16) float g_partZ[8 * NROWS];

// ---------------- helpers ----------------
__device__ __forceinline__ float ex2f(float x) {
    float r; asm("ex2.approx.ftz.f32 %0, %1;" : "=f"(r) : "f"(x)); return r;
}
__device__ __forceinline__ unsigned long long pk2(float a, float b) {
    unsigned long long r; asm("mov.b64 %0, {%1, %2};" : "=l"(r) : "f"(a), "f"(b)); return r;
}
__device__ __forceinline__ void up2(unsigned long long v, float& a, float& b) {
    asm("mov.b64 {%0, %1}, %2;" : "=f"(a), "=f"(b) : "l"(v));
}
__device__ __forceinline__ void fma2(unsigned long long& d, unsigned long long a, unsigned long long b) {
    asm("fma.rn.f32x2 %0, %1, %2, %0;" : "+l"(d) : "l"(a), "l"(b));
}
__device__ __forceinline__ void lds2u64(const float* p, unsigned long long& a, unsigned long long& b) {
    unsigned sa = (unsigned)__cvta_generic_to_shared(p);
    asm volatile("ld.shared.v2.u64 {%0, %1}, [%2];" : "=l"(a), "=l"(b) : "r"(sa));
}
__device__ __forceinline__ unsigned long long lds1u64(const float* p) {
    unsigned sa = (unsigned)__cvta_generic_to_shared(p);
    unsigned long long r;
    asm volatile("ld.shared.b64 %0, [%1];" : "=l"(r) : "r"(sa));
    return r;
}

// ---------------- 1) pack adjacency ----------------
__global__ void __launch_bounds__(256) pack_adj_kernel(const int* __restrict__ adj) {
    const int lane = threadIdx.x & 31;
    const int wid = (blockIdx.x * blockDim.x + threadIdx.x) >> 5;
    const int nWarps = (gridDim.x * blockDim.x) >> 5;
    for (int w = wid; w < NROWS * 256; w += nWarps) {
        int v = adj[(size_t)w * 32 + lane];
        unsigned b = __ballot_sync(0xffffffffu, v > 0);
        if (lane == 0) g_mask[w] = b;
    }
}

// ---------------- 2) h = x @ Wh[head] (8192x512x64) ----------------
__global__ void __launch_bounds__(256) gemm64_kernel(const float* __restrict__ X,
                                                     const float* __restrict__ WhAll) {
    const int head = blockIdx.y;
    const float* W = WhAll + head * (512 * 64);
    float* C = g_h + head * (NROWS * 64);
    const int r0 = blockIdx.x * 64;
    const int tid = threadIdx.x;
    __shared__ float4 As4[512];
    __shared__ float4 Bs4[512];
    float* As = (float*)As4;
    const int tr = tid >> 4, tc = tid & 15;
    const int lm = tid & 63, kg = tid >> 6;
    float acc[4][4];
#pragma unroll
    for (int i = 0; i < 4; i++)
#pragma unroll
        for (int j = 0; j < 4; j++) acc[i][j] = 0.f;

    for (int kt = 0; kt < 512; kt += 32) {
        __syncthreads();
        const float* xb = X + (size_t)(r0 + lm) * 512 + kt + kg * 8;
        float4 a0 = ((const float4*)xb)[0];
        float4 a1 = ((const float4*)xb)[1];
        As[(kg * 8 + 0) * 64 + lm] = a0.x; As[(kg * 8 + 1) * 64 + lm] = a0.y;
        As[(kg * 8 + 2) * 64 + lm] = a0.z; As[(kg * 8 + 3) * 64 + lm] = a0.w;
        As[(kg * 8 + 4) * 64 + lm] = a1.x; As[(kg * 8 + 5) * 64 + lm] = a1.y;
        As[(kg * 8 + 6) * 64 + lm] = a1.z; As[(kg * 8 + 7) * 64 + lm] = a1.w;
        const float4* wsrc = (const float4*)(W + kt * 64);
        Bs4[tid] = wsrc[tid];
        Bs4[tid + 256] = wsrc[tid + 256];
        __syncthreads();
#pragma unroll
        for (int kk = 0; kk < 32; kk++) {
            float4 av = As4[kk * 16 + tr];
            float4 bv = Bs4[kk * 16 + tc];
            float aa[4] = {av.x, av.y, av.z, av.w};
            float bb[4] = {bv.x, bv.y, bv.z, bv.w};
#pragma unroll
            for (int i = 0; i < 4; i++)
#pragma unroll
                for (int j = 0; j < 4; j++) acc[i][j] += aa[i] * bb[j];
        }
    }
#pragma unroll
    for (int i = 0; i < 4; i++) {
        float4 o = make_float4(acc[i][0], acc[i][1], acc[i][2], acc[i][3]);
        *(float4*)(C + (size_t)(r0 + tr * 4 + i) * 64 + tc * 4) = o;
    }
}

// ---------------- 3) f1/f2 (log2-scaled) ----------------
__global__ void __launch_bounds__(256) f1f2_heads_kernel(const float* __restrict__ ah) {
    const int head = blockIdx.y;
    const float* H = g_h + head * (NROWS * 64);
    const float* a = ah + head * 128;
    const int lane = threadIdx.x & 31;
    const int row = blockIdx.x * 8 + (threadIdx.x >> 5);
    float h0 = H[row * 64 + lane], h1 = H[row * 64 + 32 + lane];
    float s1 = h0 * a[lane] + h1 * a[32 + lane];
    float s2 = h0 * a[64 + lane] + h1 * a[96 + lane];
#pragma unroll
    for (int off = 16; off; off >>= 1) {
        s1 += __shfl_xor_sync(0xffffffffu, s1, off);
        s2 += __shfl_xor_sync(0xffffffffu, s2, off);
    }
    if (lane == 0) {
        g_f1[head * NROWS + row] = s1 * L2E;
        g_f2[head * NROWS + row] = s2 * L2E;
    }
}

__global__ void __launch_bounds__(256) f1f2_final_kernel(const float* __restrict__ ao) {
    const int lane = threadIdx.x & 31;
    const int row = blockIdx.x * 8 + (threadIdx.x >> 5);
    float s1 = 0.f, s2 = 0.f;
    if (lane < 16) {
        float h = g_h2[row * 16 + lane];
        s1 = h * ao[lane];
        s2 = h * ao[16 + lane];
    }
#pragma unroll
    for (int off = 16; off; off >>= 1) {
        s1 += __shfl_xor_sync(0xffffffffu, s1, off);
        s2 += __shfl_xor_sync(0xffffffffu, s2, off);
    }
    if (lane == 0) {
        g_f1[4 * NROWS + row] = s1 * L2E;
        g_f2[4 * NROWS + row] = s2 * L2E;
    }
}

// ---------------- 3b) B values per column ----------------
__global__ void __launch_bounds__(256) bvals_kernel(int layer0) {
    const int layer = layer0 + blockIdx.y;
    const int j = blockIdx.x * 256 + threadIdx.x;
    float f2 = g_f2[layer * NROWS + j];
    g_fb4[layer * NROWS + j] = make_float4(f2, ex2f(f2), ex2f(0.2f * f2), 0.f);
}

// ---------------- 4a) UNMASKED global max of f2 per layer ----------------
// gmax >= masked row max, so exponents stay <= 0; softmax shift-invariance
// makes the result mathematically identical. Kills the 8MB mask scans.
__global__ void __launch_bounds__(256) gmax_kernel(int layer0) {
    const int layer = layer0 + blockIdx.y;
    const float* __restrict__ f2 = g_f2 + layer * NROWS;
    const int tid = threadIdx.x;
    __shared__ float red[8];
    float mx = -3.0e38f;
    for (int i = tid * 4; i < NROWS; i += 1024) {
        float4 v = *(const float4*)&f2[i];
        mx = fmaxf(fmaxf(mx, fmaxf(v.x, v.y)), fmaxf(v.z, v.w));
    }
#pragma unroll
    for (int off = 16; off; off >>= 1) mx = fmaxf(mx, __shfl_xor_sync(0xffffffffu, mx, off));
    if ((tid & 31) == 0) red[tid >> 5] = mx;
    __syncthreads();
    if (tid < 8) {
        float m = red[tid];
#pragma unroll
        for (int off = 4; off; off >>= 1) m = fmaxf(m, __shfl_xor_sync(0xffu, m, off));
        if (tid == 0) g_gmax[layer] = m;
    }
}

// ---------------- 4b) per-row A values from gmax ----------------
__global__ void __launch_bounds__(256) avals_kernel(int layer0) {
    const int layer = layer0 + blockIdx.y;
    const int row = blockIdx.x * 256 + threadIdx.x;
    const float gm = g_gmax[layer];
    float f1v = g_f1[layer * NROWS + row];
    float s = f1v + gm;
    float m = fmaxf(s, 0.2f * s);
    g_a[layer * NROWS + row] = make_float2(ex2f(f1v - m), ex2f(0.2f * f1v - m));
}

// ---------------- 5) head attention as tiled GEMM over materialized P ----------
#define PSTRIDE 132
__global__ void __launch_bounds__(128) attn_heads_gemm() {
    const int head = blockIdx.y;
    const int split = blockIdx.z;
    const int r0 = blockIdx.x * 128;
    const int tid = threadIdx.x;
    const int tr = tid >> 3;          // 0..15 -> rows tr*8..+7
    const int tc = tid & 7;           // 0..7  -> cols tc*8..+7
    const int jj = tid & 31;          // P-build column
    const int quarter = tid >> 5;     // P-build row quarter

    __shared__ float Ps[32 * PSTRIDE];
    __shared__ float Hs[32 * 64];
    __shared__ float f1s[128], Aps[128], Ams[128];
    __shared__ unsigned mws[128];

    if (tid < 128) {
        f1s[tid] = g_f1[head * NROWS + r0 + tid];
        float2 av = g_a[head * NROWS + r0 + tid];
        Aps[tid] = av.x; Ams[tid] = av.y;
    }

    unsigned long long acc[8][4];
#pragma unroll
    for (int r = 0; r < 8; r++)
#pragma unroll
        for (int c = 0; c < 4; c++) acc[r][c] = 0ull;
    float zrow = 0.f;

    const int jbase = split * 2048;
    for (int ch = 0; ch < 64; ch++) {
        const int j0 = jbase + ch * 32;
        __syncthreads();
        {
            const float4* src = (const float4*)(g_h + (size_t)head * NROWS * 64 + (size_t)j0 * 64);
            float4* dst = (float4*)Hs;
#pragma unroll
            for (int v = 0; v < 4; v++) dst[tid + 128 * v] = src[tid + 128 * v];
        }
        mws[tid] = g_mask[(size_t)(r0 + tid) * 256 + (j0 >> 5)];
        float4 fb = g_fb4[head * NROWS + j0 + jj];
        const float f2r = fb.x, Bpr = fb.y, Bmr = fb.z;
        __syncthreads();
        {
            const int i0 = quarter * 32;
            float* prow = Ps + jj * PSTRIDE;
#pragma unroll
            for (int ib = 0; ib < 32; ib += 4) {
                float pv[4];
#pragma unroll
                for (int ii = 0; ii < 4; ii++) {
                    const int i = i0 + ib + ii;
                    float s = f1s[i] + f2r;
                    bool pos = s >= 0.f;
                    float a = pos ? Aps[i] : Ams[i];
                    float b = pos ? Bpr : Bmr;
                    pv[ii] = ((mws[i] >> jj) & 1u) ? a * b : 0.f;
                }
                *(float4*)(prow + i0 + ib) = make_float4(pv[0], pv[1], pv[2], pv[3]);
            }
        }
        __syncthreads();
#pragma unroll 2
        for (int k = 0; k < 32; k++) {
            float4 pa = *(const float4*)(Ps + k * PSTRIDE + tr * 8);
            float4 pb = *(const float4*)(Ps + k * PSTRIDE + tr * 8 + 4);
            unsigned long long h0, h1, h2, h3;
            lds2u64(Hs + k * 64 + tc * 8, h0, h1);
            lds2u64(Hs + k * 64 + tc * 8 + 4, h2, h3);
            unsigned long long p2[8];
            p2[0] = pk2(pa.x, pa.x); p2[1] = pk2(pa.y, pa.y);
            p2[2] = pk2(pa.z, pa.z); p2[3] = pk2(pa.w, pa.w);
            p2[4] = pk2(pb.x, pb.x); p2[5] = pk2(pb.y, pb.y);
            p2[6] = pk2(pb.z, pb.z); p2[7] = pk2(pb.w, pb.w);
#pragma unroll
            for (int r = 0; r < 8; r++) {
                fma2(acc[r][0], p2[r], h0);
                fma2(acc[r][1], p2[r], h1);
                fma2(acc[r][2], p2[r], h2);
                fma2(acc[r][3], p2[r], h3);
            }
        }
        {
            float zs = 0.f;
#pragma unroll 8
            for (int k = 0; k < 32; k++) zs += Ps[k * PSTRIDE + tid];
            zrow += zs;
        }
    }
    const int base = (split * 4 + head) * NROWS;
#pragma unroll
    for (int r = 0; r < 8; r++) {
        const int row = r0 + tr * 8 + r;
        float v[8];
        up2(acc[r][0], v[0], v[1]);
        up2(acc[r][1], v[2], v[3]);
        up2(acc[r][2], v[4], v[5]);
        up2(acc[r][3], v[6], v[7]);
        float* op = g_hp + ((size_t)base + row) * 64 + tc * 8;
        *(float4*)op = make_float4(v[0], v[1], v[2], v[3]);
        *(float4*)(op + 4) = make_float4(v[4], v[5], v[6], v[7]);
    }
    g_hpZ[base + r0 + tid] = zrow;
}

// ---------------- 5b) reduce head partials -> xcat (LR 0.01) ----------------
__global__ void __launch_bounds__(256) reduce_heads_kernel() {
    const int idx = blockIdx.x * 256 + threadIdx.x;
    const int row = idx >> 8;
    const int cc = idx & 255;
    const int head = cc >> 6;
    const int col = cc & 63;
    float s = 0.f, z = 0.f;
#pragma unroll
    for (int sp = 0; sp < 4; sp++) {
        s += g_hp[((size_t)(sp * 4 + head) * NROWS + row) * 64 + col];
        z += g_hpZ[(sp * 4 + head) * NROWS + row];
    }
    float v = s / z;
    g_xcat[(size_t)row * 256 + cc] = fmaxf(v, 0.01f * v);
}

// ---------------- 6) h2 = xcat @ Wo ----------------
__global__ void __launch_bounds__(128) gemm2_kernel(const float* __restrict__ Wo) {
    __shared__ float Ws[256 * 16];
    const int tid = threadIdx.x;
    for (int i = tid; i < 4096; i += 128) Ws[i] = Wo[i];
    __syncthreads();
    const int row = blockIdx.x * 128 + tid;
    const float* xr = g_xcat + (size_t)row * 256;
    float acc[16];
#pragma unroll
    for (int j = 0; j < 16; j++) acc[j] = 0.f;
    for (int k = 0; k < 256; k += 4) {
        float4 xv = *(const float4*)(xr + k);
#pragma unroll
        for (int j = 0; j < 16; j++) {
            acc[j] += xv.x * Ws[(k + 0) * 16 + j];
            acc[j] += xv.y * Ws[(k + 1) * 16 + j];
            acc[j] += xv.z * Ws[(k + 2) * 16 + j];
            acc[j] += xv.w * Ws[(k + 3) * 16 + j];
        }
    }
#pragma unroll
    for (int j = 0; j < 16; j++) g_h2[row * 16 + j] = acc[j];
}

// ---------------- 7) final attention (FFMA2 tiled GEMM) ----------------
__global__ void __launch_bounds__(128) attn_final_gemm() {
    const int split = blockIdx.y;
    const int r0 = blockIdx.x * 128;
    const int tid = threadIdx.x;
    const int tr = tid >> 3;
    const int tc = tid & 7;
    const int jj = tid & 31;
    const int quarter = tid >> 5;

    __shared__ float Ps[32 * PSTRIDE];
    __shared__ float Hs[32 * 16];
    __shared__ float f1s[128], Aps[128], Ams[128];
    __shared__ unsigned mws[128];

    if (tid < 128) {
        f1s[tid] = g_f1[4 * NROWS + r0 + tid];
        float2 av = g_a[4 * NROWS + r0 + tid];
        Aps[tid] = av.x; Ams[tid] = av.y;
    }
    unsigned long long acc[8];
#pragma unroll
    for (int r = 0; r < 8; r++) acc[r] = 0ull;
    float zrow = 0.f;

    const int jbase = split * 1024;
    for (int ch = 0; ch < 32; ch++) {
        const int j0 = jbase + ch * 32;
        __syncthreads();
        {
            const float4* src = (const float4*)(g_h2 + (size_t)j0 * 16);
            if (tid < 128) ((float4*)Hs)[tid] = src[tid];
        }
        mws[tid] = g_mask[(size_t)(r0 + tid) * 256 + (j0 >> 5)];
        float4 fb = g_fb4[4 * NROWS + j0 + jj];
        const float f2r = fb.x, Bpr = fb.y, Bmr = fb.z;
        __syncthreads();
        {
            const int i0 = quarter * 32;
            float* prow = Ps + jj * PSTRIDE;
#pragma unroll
            for (int ib = 0; ib < 32; ib += 4) {
                float pv[4];
#pragma unroll
                for (int ii = 0; ii < 4; ii++) {
                    const int i = i0 + ib + ii;
                    float s = f1s[i] + f2r;
                    bool pos = s >= 0.f;
                    float a = pos ? Aps[i] : Ams[i];
                    float b = pos ? Bpr : Bmr;
                    pv[ii] = ((mws[i] >> jj) & 1u) ? a * b : 0.f;
                }
                *(float4*)(prow + i0 + ib) = make_float4(pv[0], pv[1], pv[2], pv[3]);
            }
        }
        __syncthreads();
#pragma unroll 2
        for (int k = 0; k < 32; k++) {
            float4 pa = *(const float4*)(Ps + k * PSTRIDE + tr * 8);
            float4 pb = *(const float4*)(Ps + k * PSTRIDE + tr * 8 + 4);
            unsigned long long h0 = lds1u64(Hs + k * 16 + tc * 2);
            unsigned long long p2[8];
            p2[0] = pk2(pa.x, pa.x); p2[1] = pk2(pa.y, pa.y);
            p2[2] = pk2(pa.z, pa.z); p2[3] = pk2(pa.w, pa.w);
            p2[4] = pk2(pb.x, pb.x); p2[5] = pk2(pb.y, pb.y);
            p2[6] = pk2(pb.z, pb.z); p2[7] = pk2(pb.w, pb.w);
#pragma unroll
            for (int r = 0; r < 8; r++) fma2(acc[r], p2[r], h0);
        }
        {
            float zs = 0.f;
#pragma unroll 8
            for (int k = 0; k < 32; k++) zs += Ps[k * PSTRIDE + tid];
            zrow += zs;
        }
    }
#pragma unroll
    for (int r = 0; r < 8; r++) {
        const int row = r0 + tr * 8 + r;
        *(unsigned long long*)&g_part[((size_t)split * NROWS + row) * 16 + tc * 2] = acc[r];
    }
    g_partZ[split * NROWS + r0 + tid] = zrow;
}

// ---------------- 8) reduce partials -> output ----------------
__global__ void __launch_bounds__(256) reduce_kernel(float* __restrict__ out) {
    const int idx = blockIdx.x * 256 + threadIdx.x;
    const int row = idx >> 4;
    float s = 0.f, z = 0.f;
#pragma unroll
    for (int c = 0; c < 8; c++) {
        s += g_part[((size_t)c * NROWS + row) * 16 + (idx & 15)];
        z += g_partZ[c * NROWS + row];
    }
    out[idx] = s / z;
}

extern "C" void kernel_launch(void* const* d_in, const int* in_sizes, int n_in,
                              void* d_out, int out_size) {
    const float* x   = (const float*)d_in[0];
    const int*   adj = (const int*)d_in[1];
    const float* Wh  = (const float*)d_in[2];
    const float* ah  = (const float*)d_in[3];
    const float* Wo  = (const float*)d_in[4];
    const float* ao  = (const float*)d_in[5];
    float* out = (float*)d_out;

    pack_adj_kernel<<<2048, 256>>>(adj);
    gemm64_kernel<<<dim3(128, 4), 256>>>(x, Wh);
    f1f2_heads_kernel<<<dim3(1024, 4), 256>>>(ah);
    bvals_kernel<<<dim3(32, 4), 256>>>(0);
    gmax_kernel<<<dim3(1, 4), 256>>>(0);
    avals_kernel<<<dim3(32, 4), 256>>>(0);
    attn_heads_gemm<<<dim3(64, 4, 4), 128>>>();
    reduce_heads_kernel<<<8192, 256>>>();
    gemm2_kernel<<<64, 128>>>(Wo);
    f1f2_final_kernel<<<1024, 256>>>(ao);
    bvals_kernel<<<dim3(32, 1), 256>>>(4);
    gmax_kernel<<<dim3(1, 1), 256>>>(4);
    avals_kernel<<<dim3(32, 1), 256>>>(4);
    attn_final_gemm<<<dim3(64, 8), 128>>>();
    reduce_kernel<<<512, 256>>>(out);
}